// round 17
// baseline (speedup 1.0000x reference)
#include <cuda_runtime.h>
#include <math.h>

// Problem dims: B=32, T=1024, D=512, H=256 (2H == D)

// ---------------- scratch (device globals; no allocations allowed) ----------------
__device__ float g_xg_f[33554432];   // [B*T, 4H] = 32768 x 1024
__device__ float g_xg_b[33554432];
__device__ float g_xe[16777216];     // [B, T, 512]
__device__ float g_proj[16777216];   // [B, T, 512]
__device__ float g_L[33554432];      // [B, T, T] = 32 x 1024 x 1024
__device__ unsigned g_mask_flags;
__device__ unsigned char g_mask[32768];

__global__ void reset_kernel() { g_mask_flags = 0u; }

// ---- mask dtype detection (int32 / float32 / uint8 bool) ----
__global__ void mask_detect_kernel(const unsigned* __restrict__ m) {
    int i = blockIdx.x * 256 + threadIdx.x;  // 8192 words = 32768 bytes, safe for all dtypes
    unsigned v = m[i];
    unsigned f = 0;
    if (v != 0u && v != 1u)           f |= 1u;
    if (v != 0u && v != 0x3F800000u)  f |= 2u;
    if (f) atomicOr(&g_mask_flags, f);
}

__global__ void mask_expand_kernel(const void* __restrict__ m) {
    int i = blockIdx.x * 256 + threadIdx.x;  // 32768
    unsigned flags = g_mask_flags;
    unsigned char r;
    if ((flags & 1u) == 0u)        r = (unsigned char)(((const unsigned*)m)[i] != 0u);
    else if ((flags & 2u) == 0u)   r = (unsigned char)(((const float*)m)[i] != 0.0f);
    else                           r = ((const unsigned char*)m)[i] ? 1 : 0;
    g_mask[i] = r;
}

__device__ __forceinline__ float sigmoidf_(float x) { return 1.0f / (1.0f + __expf(-x)); }
// fast tanh via MUFU exp: tanh(x) = 1 - 2/(e^{2x}+1)   (rel err ~1e-7)
__device__ __forceinline__ float tanhf_(float x) {
    return 1.0f - 2.0f / (__expf(2.0f * x) + 1.0f);
}

__device__ __forceinline__ unsigned smem_u32(const void* p) {
    unsigned a;
    asm("{ .reg .u64 t; cvta.to.shared.u64 t, %1; cvt.u32.u64 %0, t; }" : "=r"(a) : "l"(p));
    return a;
}

// ---- packed f32x2 helpers (FFMA2: 2 fp32 MACs per fma-pipe slot, exact fp32 rounding) ----
__device__ __forceinline__ unsigned long long pack2(float lo, float hi) {
    unsigned long long r;
    asm("mov.b64 %0, {%1, %2};" : "=l"(r) : "f"(lo), "f"(hi));
    return r;
}
__device__ __forceinline__ void fma2(unsigned long long& d, unsigned long long a,
                                     unsigned long long b) {
    asm("fma.rn.f32x2 %0, %1, %2, %0;" : "+l"(d) : "l"(a), "l"(b));
}
__device__ __forceinline__ float2 unpack2(unsigned long long v) {
    float2 r;
    asm("mov.b64 {%0, %1}, %2;" : "=f"(r.x), "=f"(r.y) : "l"(v));
    return r;
}

// ---------------- generic fp32 SGEMM: C = A @ op(B) (+bias), 128x128 tile ----------------
template<bool TRANSB, bool BIAS>
__global__ __launch_bounds__(256) void sgemm_kernel(
    const float* __restrict__ A, const float* __restrict__ B,
    const float* __restrict__ bias, float* __restrict__ C,
    int M, int N, int K, long sA, long sB, long sC)
{
    __shared__ float As[2][8][128];
    __shared__ float Bs[2][8][128];

    long bz = blockIdx.z;
    A += bz * sA; B += bz * sB; C += bz * sC;

    int mBase = blockIdx.y * 128;
    int nBase = blockIdx.x * 128;
    int tid  = threadIdx.x;
    int warp = tid >> 5, lane = tid & 31;
    int wr = warp >> 2, wc = warp & 3;
    int lr = lane >> 2, lc = lane & 3;
    int row0 = wr * 64 + lr * 8;
    int col0 = wc * 32 + lc * 8;

    unsigned long long acc2[8][4];
#pragma unroll
    for (int i = 0; i < 8; ++i)
#pragma unroll
        for (int j = 0; j < 4; ++j) acc2[i][j] = 0ull;

    int arow = tid >> 1;
    int akq  = (tid & 1) * 4;
    const float* Aptr = A + (long)(mBase + arow) * K + akq;

    const float* Bptr;
    int brow = 0, bkq = 0, bk = 0, bnq = 0;
    if (TRANSB) {
        brow = tid >> 1; bkq = (tid & 1) * 4;
        Bptr = B + (long)(nBase + brow) * K + bkq;
    } else {
        bk = tid >> 5; bnq = lane * 4;
        Bptr = B + (long)bk * N + nBase + bnq;
    }

    {
        float4 av = *(const float4*)Aptr; Aptr += 8;
        As[0][akq + 0][arow] = av.x; As[0][akq + 1][arow] = av.y;
        As[0][akq + 2][arow] = av.z; As[0][akq + 3][arow] = av.w;
        if (TRANSB) {
            float4 bv = *(const float4*)Bptr; Bptr += 8;
            Bs[0][bkq + 0][brow] = bv.x; Bs[0][bkq + 1][brow] = bv.y;
            Bs[0][bkq + 2][brow] = bv.z; Bs[0][bkq + 3][brow] = bv.w;
        } else {
            float4 bv = *(const float4*)Bptr; Bptr += (long)8 * N;
            *(float4*)&Bs[0][bk][bnq] = bv;
        }
    }
    __syncthreads();

    int p = 0;
    for (int k0 = 0; k0 < K; k0 += 8) {
        bool nx = (k0 + 8) < K;
        float4 av2, bv2;
        if (nx) {
            av2 = *(const float4*)Aptr; Aptr += 8;
            if (TRANSB) { bv2 = *(const float4*)Bptr; Bptr += 8; }
            else        { bv2 = *(const float4*)Bptr; Bptr += (long)8 * N; }
        }

#pragma unroll
        for (int k = 0; k < 8; ++k) {
            float4 a0 = *(const float4*)&As[p][k][row0];
            float4 a1 = *(const float4*)&As[p][k][row0 + 4];
            ulonglong2 bq0 = *(const ulonglong2*)&Bs[p][k][col0];
            ulonglong2 bq1 = *(const ulonglong2*)&Bs[p][k][col0 + 4];
            unsigned long long b2[4] = {bq0.x, bq0.y, bq1.x, bq1.y};
            float a[8] = {a0.x, a0.y, a0.z, a0.w, a1.x, a1.y, a1.z, a1.w};
#pragma unroll
            for (int i = 0; i < 8; ++i) {
                unsigned long long ai = pack2(a[i], a[i]);
                fma2(acc2[i][0], ai, b2[0]);
                fma2(acc2[i][1], ai, b2[1]);
                fma2(acc2[i][2], ai, b2[2]);
                fma2(acc2[i][3], ai, b2[3]);
            }
        }

        if (nx) {
            int q = p ^ 1;
            As[q][akq + 0][arow] = av2.x; As[q][akq + 1][arow] = av2.y;
            As[q][akq + 2][arow] = av2.z; As[q][akq + 3][arow] = av2.w;
            if (TRANSB) {
                Bs[q][bkq + 0][brow] = bv2.x; Bs[q][bkq + 1][brow] = bv2.y;
                Bs[q][bkq + 2][brow] = bv2.z; Bs[q][bkq + 3][brow] = bv2.w;
            } else {
                *(float4*)&Bs[q][bk][bnq] = bv2;
            }
        }
        __syncthreads();
        p ^= 1;
    }

    float bb[8];
#pragma unroll
    for (int j = 0; j < 8; ++j) bb[j] = 0.0f;
    if (BIAS) {
#pragma unroll
        for (int j = 0; j < 8; ++j) bb[j] = bias[nBase + col0 + j];
    }
#pragma unroll
    for (int i = 0; i < 8; ++i) {
        float2 q0 = unpack2(acc2[i][0]);
        float2 q1 = unpack2(acc2[i][1]);
        float2 q2 = unpack2(acc2[i][2]);
        float2 q3 = unpack2(acc2[i][3]);
        float* cp = C + (long)(mBase + row0 + i) * N + nBase + col0;
        float4 o0 = make_float4(q0.x + bb[0], q0.y + bb[1], q1.x + bb[2], q1.y + bb[3]);
        float4 o1 = make_float4(q2.x + bb[4], q2.y + bb[5], q3.x + bb[6], q3.y + bb[7]);
        *(float4*)cp = o0;
        *(float4*)(cp + 4) = o1;
    }
}

// ---------------- cluster-based bidirectional LSTM recurrence ----------------
// 16 clusters of 8 CTAs. Per-step h exchange: scalar st.shared::cluster pushes +
// fence.acq_rel.cluster (release) + plain mbarrier arrive; waiter: try_wait +
// fence.acq_rel.cluster (acquire). Standard fence/relaxed-flag/fence pattern —
// no barrier.cluster in the loop (no per-step L1D flush).
__global__ __launch_bounds__(256, 1) __cluster_dims__(8, 1, 1)
void lstm_cluster_kernel(const float* __restrict__ xg_f, const float* __restrict__ xg_b,
                         const float* __restrict__ Whh_f, const float* __restrict__ Whh_b,
                         float* __restrict__ xe)
{
    extern __shared__ float sm[];
    float* hB     = sm;            // [2 buf][4 b][256 k]  floats 0..2047
    float* part   = sm + 2048;     // [8 slice][4 b][128 rows] floats 2048..6143
    float* hStage = sm + 6144;     // [4 b][32 u] floats 6144..6271
    // mbar[2] at byte offset 25088 (8B aligned)

    int tid = threadIdx.x;
    int cid = blockIdx.x >> 3;
    int dir = cid >> 3;
    int bg  = cid & 7;
    unsigned rk;
    asm("mov.u32 %0, %%cluster_ctarank;" : "=r"(rk));
    int u0 = (int)rk * 32;

    const float* xg  = dir ? xg_b : xg_f;
    const float* Whh = dir ? Whh_b : Whh_f;

    unsigned base_u32 = smem_u32(sm);
    unsigned hb_u32   = base_u32;
    unsigned mbar_u32 = base_u32 + 25088u;

    int sl = tid >> 5;          // k-slice 0..7
    int rq = tid & 31;          // row quad: rows 4rq..4rq+3 (row = gate*32 + unit_local)
    int r0 = rq * 4;
    int kbase = sl * 32;
    int cb = tid >> 5;          // cell-update batch (tid<128)
    int cu = tid & 31;          // cell-update unit
    int Bglob = bg * 4 + cb;

    // push role: peer pr = tid>>5, slot = tid&31 -> (batch pb, unit block pu4)
    int pr  = tid >> 5;
    int pb  = (tid & 31) >> 3;
    int pu4 = ((tid & 31) & 7) * 4;
    unsigned rem_hb, rem_mbar;
    asm("mapa.shared::cluster.u32 %0, %1, %2;" : "=r"(rem_hb)   : "r"(hb_u32),   "r"(pr));
    asm("mapa.shared::cluster.u32 %0, %1, %2;" : "=r"(rem_mbar) : "r"(mbar_u32), "r"(pr));

    // ---- load W slice into registers, packed as f32x2 row-pairs ----
    unsigned long long w2[32][2];
    {
        int gate = r0 >> 5, ul0 = r0 & 31;
        const float* p0 = Whh + (size_t)(gate * 256 + u0 + ul0) * 256 + kbase;
#pragma unroll
        for (int q = 0; q < 8; ++q) {
            float4 wa = *(const float4*)(p0 + 0 * 256 + q * 4);
            float4 wb = *(const float4*)(p0 + 1 * 256 + q * 4);
            float4 wc = *(const float4*)(p0 + 2 * 256 + q * 4);
            float4 wd = *(const float4*)(p0 + 3 * 256 + q * 4);
            w2[q * 4 + 0][0] = pack2(wa.x, wb.x); w2[q * 4 + 0][1] = pack2(wc.x, wd.x);
            w2[q * 4 + 1][0] = pack2(wa.y, wb.y); w2[q * 4 + 1][1] = pack2(wc.y, wd.y);
            w2[q * 4 + 2][0] = pack2(wa.z, wb.z); w2[q * 4 + 2][1] = pack2(wc.z, wd.z);
            w2[q * 4 + 3][0] = pack2(wa.w, wb.w); w2[q * 4 + 3][1] = pack2(wc.w, wd.w);
        }
    }

    // h buffer 0 = 0; init mbarriers (256 arrivals each per phase)
    for (int i = tid; i < 1024; i += 256) hB[i] = 0.0f;
    if (tid == 0) {
        asm volatile("mbarrier.init.shared.b64 [%0], %1;" :: "r"(mbar_u32)      , "r"(256u) : "memory");
        asm volatile("mbarrier.init.shared.b64 [%0], %1;" :: "r"(mbar_u32 + 8u), "r"(256u) : "memory");
    }
    __syncthreads();
    // one-time cluster barrier: peers' mbarrier init + hB zeros visible before any arrive
    asm volatile("barrier.cluster.arrive.aligned;" ::: "memory");
    asm volatile("barrier.cluster.wait.aligned;" ::: "memory");

    float c_state = 0.0f;

    for (int s = 0; s < 1024; ++s) {
        int t = dir ? (1023 - s) : s;
        int cur = s & 1;
        int nb  = cur ^ 1;

        // prefetch xg for this step's cell update
        float xgi = 0.f, xgf = 0.f, xgg = 0.f, xgo = 0.f;
        if (tid < 128) {
            size_t base = ((size_t)Bglob * 1024 + (size_t)t) * 1024 + u0 + cu;
            xgi = __ldg(&xg[base]);
            xgf = __ldg(&xg[base + 256]);
            xgg = __ldg(&xg[base + 512]);
            xgo = __ldg(&xg[base + 768]);
        }

        // wait for hB[cur] to be fully pushed (during step s-1); s=0 reads zeros.
        // acquire side of the fence/relaxed-flag/fence pattern.
        if (s > 0) {
            unsigned mb = mbar_u32 + (unsigned)(cur * 8);
            unsigned parity = (unsigned)(((s - 1) >> 1) & 1);
            asm volatile(
                "{\n\t"
                ".reg .pred P1;\n\t"
                "WL_%=:\n\t"
                "mbarrier.try_wait.parity.acquire.cta.shared::cta.b64 P1, [%0], %1, 0x989680;\n\t"
                "@P1 bra.uni WD_%=;\n\t"
                "bra.uni WL_%=;\n\t"
                "WD_%=:\n\t"
                "}"
                :: "r"(mb), "r"(parity) : "memory");
            asm volatile("fence.acq_rel.cluster;" ::: "memory");
        }

        // partial GEMV: 4 row-pairs x 4 batches over this thread's 32-k slice
        unsigned long long ac2[4][2];
#pragma unroll
        for (int b = 0; b < 4; ++b) { ac2[b][0] = 0ull; ac2[b][1] = 0ull; }

        const float* hc = hB + cur * 1024 + kbase;
#pragma unroll
        for (int q = 0; q < 8; ++q) {
            float hv[4][4];
#pragma unroll
            for (int b = 0; b < 4; ++b)
                *(float4*)hv[b] = *(const float4*)(hc + b * 256 + q * 4);
#pragma unroll
            for (int e = 0; e < 4; ++e) {
                int kk = q * 4 + e;
#pragma unroll
                for (int b = 0; b < 4; ++b) {
                    unsigned long long h2 = pack2(hv[b][e], hv[b][e]);
                    fma2(ac2[b][0], h2, w2[kk][0]);
                    fma2(ac2[b][1], h2, w2[kk][1]);
                }
            }
        }
#pragma unroll
        for (int b = 0; b < 4; ++b) {
            float2 lo = unpack2(ac2[b][0]);
            float2 hi = unpack2(ac2[b][1]);
            *(float4*)&part[(sl * 4 + b) * 128 + r0] =
                make_float4(lo.x, lo.y, hi.x, hi.y);
        }
        __syncthreads();

        if (tid < 128) {
            float d0 = 0.f, d1 = 0.f, d2 = 0.f, d3 = 0.f;
#pragma unroll
            for (int s2 = 0; s2 < 8; ++s2) {
                const float* pp = part + (s2 * 4 + cb) * 128 + cu;
                d0 += pp[0];
                d1 += pp[32];
                d2 += pp[64];
                d3 += pp[96];
            }
            float gi = d0 + xgi, gf = d1 + xgf, gG = d2 + xgg, go = d3 + xgo;
            c_state = sigmoidf_(gf) * c_state + sigmoidf_(gi) * tanhf_(gG);
            float h = sigmoidf_(go) * tanhf_(c_state);
            hStage[cb * 32 + cu] = h;
            xe[((size_t)Bglob * 1024 + (size_t)t) * 512 + dir * 256 + u0 + cu] = h;
        }
        __syncthreads();

        // DSMEM push: each thread ships 4 floats to one peer (proven scalar form),
        // release fence, then plain arrive on the peer's mbar[nb].
        {
            const float* hs = &hStage[pb * 32 + pu4];
            unsigned dst = rem_hb + (unsigned)((nb * 1024 + pb * 256 + u0 + pu4) * 4);
            asm volatile("st.shared::cluster.f32 [%0], %1;" :: "r"(dst),       "f"(hs[0]) : "memory");
            asm volatile("st.shared::cluster.f32 [%0], %1;" :: "r"(dst + 4u),  "f"(hs[1]) : "memory");
            asm volatile("st.shared::cluster.f32 [%0], %1;" :: "r"(dst + 8u),  "f"(hs[2]) : "memory");
            asm volatile("st.shared::cluster.f32 [%0], %1;" :: "r"(dst + 12u), "f"(hs[3]) : "memory");
            asm volatile("fence.acq_rel.cluster;" ::: "memory");
            unsigned mb = rem_mbar + (unsigned)(nb * 8);
            asm volatile("mbarrier.arrive.shared::cluster.b64 _, [%0];" :: "r"(mb) : "memory");
        }
    }

    // no CTA may exit while peers' incoming remote stores/arrives are in flight
    asm volatile("barrier.cluster.arrive.aligned;" ::: "memory");
    asm volatile("barrier.cluster.wait.aligned;" ::: "memory");
}

// ---------------- masked softmax over rows of L ----------------
__global__ __launch_bounds__(256) void softmax_kernel(float* __restrict__ L)
{
    int i = blockIdx.x, b = blockIdx.y;
    float* row = L + ((long)b * 1024 + i) * 1024;
    int tid = threadIdx.x;

    if (g_mask[b * 1024 + i]) {
        const float u = 1.0f / 1024.0f;
#pragma unroll
        for (int q = 0; q < 4; ++q) row[tid + q * 256] = u;
        return;
    }

    __shared__ float red[8];
    float v[4];
    float m = -1e30f;
#pragma unroll
    for (int q = 0; q < 4; ++q) { v[q] = row[tid + q * 256]; m = fmaxf(m, v[q]); }
#pragma unroll
    for (int o = 16; o; o >>= 1) m = fmaxf(m, __shfl_xor_sync(0xffffffffu, m, o));
    int warp = tid >> 5, lane = tid & 31;
    if (lane == 0) red[warp] = m;
    __syncthreads();
    if (warp == 0) {
        float x = (lane < 8) ? red[lane] : -1e30f;
#pragma unroll
        for (int o = 4; o; o >>= 1) x = fmaxf(x, __shfl_xor_sync(0xffffffffu, x, o));
        if (lane == 0) red[0] = x;
    }
    __syncthreads();
    m = red[0];

    float sum = 0.0f;
#pragma unroll
    for (int q = 0; q < 4; ++q) { v[q] = __expf(v[q] - m); sum += v[q]; }
#pragma unroll
    for (int o = 16; o; o >>= 1) sum += __shfl_xor_sync(0xffffffffu, sum, o);
    __syncthreads();
    if (lane == 0) red[warp] = sum;
    __syncthreads();
    if (warp == 0) {
        float x = (lane < 8) ? red[lane] : 0.0f;
#pragma unroll
        for (int o = 4; o; o >>= 1) x += __shfl_xor_sync(0xffffffffu, x, o);
        if (lane == 0) red[0] = x;
    }
    __syncthreads();
    float inv = 1.0f / red[0];
#pragma unroll
    for (int q = 0; q < 4; ++q) row[tid + q * 256] = v[q] * inv;
}

// ---------------- launch ----------------
extern "C" void kernel_launch(void* const* d_in, const int* in_sizes, int n_in,
                              void* d_out, int out_size)
{
    const float* x      = (const float*)d_in[0];
    const void*  xmask  = d_in[1];
    const float* W_ih_f = (const float*)d_in[2];
    const float* W_hh_f = (const float*)d_in[3];
    const float* b_f    = (const float*)d_in[4];
    const float* W_ih_b = (const float*)d_in[5];
    const float* W_hh_b = (const float*)d_in[6];
    const float* b_b    = (const float*)d_in[7];
    const float* W_l    = (const float*)d_in[8];
    float* out = (float*)d_out;

    float *xgF, *xgB, *xe, *proj, *L;
    cudaGetSymbolAddress((void**)&xgF,  g_xg_f);
    cudaGetSymbolAddress((void**)&xgB,  g_xg_b);
    cudaGetSymbolAddress((void**)&xe,   g_xe);
    cudaGetSymbolAddress((void**)&proj, g_proj);
    cudaGetSymbolAddress((void**)&L,    g_L);

    // 0) canonicalize mask (dtype-agnostic: int32 / float32 / uint8)
    reset_kernel<<<1, 1>>>();
    mask_detect_kernel<<<32, 256>>>((const unsigned*)xmask);
    mask_expand_kernel<<<128, 256>>>(xmask);

    // 1) input projections: xg = x2d @ W_ih^T + b   [32768 x 1024]
    sgemm_kernel<true, true><<<dim3(8, 256, 1), 256>>>(
        x, W_ih_f, b_f, xgF, 32768, 1024, 512, 0, 0, 0);
    sgemm_kernel<true, true><<<dim3(8, 256, 1), 256>>>(
        x, W_ih_b, b_b, xgB, 32768, 1024, 512, 0, 0, 0);

    // 2) bidirectional LSTM recurrence (16 clusters x 8 CTAs, mbarrier h exchange)
    int smem = 25088 + 16;  // hB+part+hStage + mbar[2]
    cudaFuncSetAttribute(lstm_cluster_kernel,
                         cudaFuncAttributeMaxDynamicSharedMemorySize, smem);
    lstm_cluster_kernel<<<128, 256, smem>>>(xgF, xgB, W_hh_f, W_hh_b, xe);

    // 3) proj = xe @ W_l^T   [32768 x 512]
    sgemm_kernel<true, false><<<dim3(4, 256, 1), 256>>>(
        xe, W_l, nullptr, proj, 32768, 512, 512, 0, 0, 0);

    // 4) L[b] = proj[b] @ xe[b]^T   batched [1024 x 1024], K=512
    sgemm_kernel<true, false><<<dim3(8, 8, 32), 256>>>(
        proj, xe, nullptr, L, 1024, 1024, 512,
        (long)1024 * 512, (long)1024 * 512, (long)1024 * 1024);

    // 5) masked softmax rows of L
    softmax_kernel<<<dim3(1024, 32), 256>>>(L);

    // 6) out[b] = A[b] @ xe[b]   batched [1024 x 512], K=1024
    sgemm_kernel<false, false><<<dim3(4, 8, 32), 256>>>(
        L, xe, nullptr, out, 1024, 512, 1024,
        (long)1024 * 1024, (long)1024 * 512, (long)1024 * 512);
}